// round 9
// baseline (speedup 1.0000x reference)
#include <cuda_runtime.h>
#include <cuda_bf16.h>

#define N_NODES 50000
#define N_EDGES 800000
#define C1 128
#define C2 256
#define NB_N ((N_NODES + 255) / 256)   // 196
#define NB_E ((N_EDGES + 255) / 256)   // 3125
#define PROBE_N 6250                   // 1/8 of nodes for the ncu probe

// ---------------- device scratch (static, no allocation) ----------------
__device__ int      g_is64;
__device__ int      g_degi[N_NODES];
__device__ float    g_dinv[N_NODES];
__device__ int      g_rowoff[N_NODES + 1];
__device__ int      g_cursor[N_NODES];
__device__ int      g_partial[256];
__device__ int2     g_csr[N_EDGES];        // {src, float_as_int(nrm)}
__device__ float    g_aggx[(long long)N_NODES * C1];  // S·X
__device__ float    g_h1[(long long)N_NODES * C1];    // relu(aggx·W1+b1)
__device__ float    g_aggh[(long long)N_NODES * C1];  // S·h1
__device__ float    g_dbg[(long long)PROBE_N * C1];   // probe scratch
__device__ float    g_logits[N_NODES];
__device__ float    g_pw[N_NODES];
__device__ unsigned g_maxkey;
__device__ float    g_sumexp;

// ---------------- helpers ----------------
__device__ __forceinline__ int edge_idx(const void* ei, long long i, int is64) {
    if (is64) return (int)((const long long*)ei)[i];
    return ((const int*)ei)[i];
}
__device__ __forceinline__ unsigned enc_f(float f) {
    unsigned u = __float_as_uint(f);
    return (u & 0x80000000u) ? ~u : (u | 0x80000000u);
}
__device__ __forceinline__ float dec_f(unsigned k) {
    unsigned u = (k & 0x80000000u) ? (k ^ 0x80000000u) : ~k;
    return __uint_as_float(u);
}

// ---------------- preprocessing ----------------
__global__ void k_sniff_init(const void* ei) {
    int i = blockIdx.x * blockDim.x + threadIdx.x;
    if (i < N_NODES) g_degi[i] = 0;
    if (i == 0) {
        g_maxkey = 0u; g_sumexp = 0.f;
        const long long* p = (const long long*)ei;
        int ok = 1;
        for (int q = 0; q < 64; q++) {
            long long v = p[q];
            if (v < 0 || v >= N_NODES) { ok = 0; break; }
        }
        g_is64 = ok;
    }
}

__global__ void k_count(const void* ei) {
    int e = blockIdx.x * blockDim.x + threadIdx.x;
    if (e >= N_EDGES) return;
    int d = edge_idx(ei, (long long)N_EDGES + e, g_is64);
    atomicAdd(&g_degi[d], 1);
}

__global__ void k_scan1() {
    __shared__ int sh[256];
    int t = threadIdx.x;
    int i = blockIdx.x * 256 + t;
    int v = (i < N_NODES) ? g_degi[i] : 0;
    if (i < N_NODES) g_dinv[i] = rsqrtf((float)(v + 1)); // +1 self loop
    sh[t] = v;
    __syncthreads();
    for (int off = 1; off < 256; off <<= 1) {
        int add = (t >= off) ? sh[t - off] : 0;
        __syncthreads();
        sh[t] += add;
        __syncthreads();
    }
    if (i < N_NODES) g_rowoff[i + 1] = sh[t];
    if (t == 255) g_partial[blockIdx.x] = sh[255];
}

__global__ void k_scan2() {
    __shared__ int sh[256];
    int t = threadIdx.x;
    int v = (t < NB_N) ? g_partial[t] : 0;
    sh[t] = v;
    __syncthreads();
    for (int off = 1; off < 256; off <<= 1) {
        int add = (t >= off) ? sh[t - off] : 0;
        __syncthreads();
        sh[t] += add;
        __syncthreads();
    }
    g_partial[t] = sh[t] - v; // exclusive
}

// final rowoff + cursor init (fused)
__global__ void k_scan3() {
    int i = blockIdx.x * blockDim.x + threadIdx.x;
    if (i == 0) { g_rowoff[0] = 0; g_cursor[0] = 0; }
    if (i < N_NODES) {
        int r = g_rowoff[i + 1] + g_partial[i >> 8];
        g_rowoff[i + 1] = r;
        if (i + 1 < N_NODES) g_cursor[i + 1] = r;
    }
}

__global__ void k_scatter(const void* ei) {
    int e = blockIdx.x * blockDim.x + threadIdx.x;
    if (e >= N_EDGES) return;
    int is64 = g_is64;
    int s = edge_idx(ei, e, is64);
    int d = edge_idx(ei, (long long)N_EDGES + e, is64);
    int pos = atomicAdd(&g_cursor[d], 1);
    g_csr[pos] = make_int2(s, __float_as_int(g_dinv[s] * g_dinv[d]));
}

// ---------------- aggregation: out = S · x  (128-dim, warp per node) ------
// out[d] = dinv[d]^2 * x[d] + sum_edges nrm * x[src]
// Fully scalarized 8-deep gather pipeline (no arrays -> no local-mem spill);
// launch_bounds(256,3) gives an 85-reg ceiling so the pipeline stays in regs.
#define AGG_LOADC(q, cq)                                        \
    {   int jj = j + (q);                                       \
        int jc = jj < (N_EDGES - 1) ? jj : (N_EDGES - 1);       \
        int2 t = g_csr[jc];                                     \
        cq = (jj < end) ? t : make_int2(d, 0);                  \
    }

__global__ void __launch_bounds__(256, 3)
k_agg128(const float* __restrict__ xin, float* __restrict__ out, int nlimit) {
    int d = (blockIdx.x * blockDim.x + threadIdx.x) >> 5;
    int lane = threadIdx.x & 31;
    if (d >= nlimit) return;

    const float4* x4 = (const float4*)xin;

    float di = g_dinv[d];
    float sl = di * di;

    float4 v0 = x4[(long long)d * 32 + lane];
    float4 acc;
    acc.x = sl * v0.x; acc.y = sl * v0.y; acc.z = sl * v0.z; acc.w = sl * v0.w;

    int j = g_rowoff[d];
    int end = g_rowoff[d + 1];

    for (; j < end; j += 8) {
        int2 c0, c1, c2, c3, c4, c5, c6, c7;
        AGG_LOADC(0, c0) AGG_LOADC(1, c1) AGG_LOADC(2, c2) AGG_LOADC(3, c3)
        AGG_LOADC(4, c4) AGG_LOADC(5, c5) AGG_LOADC(6, c6) AGG_LOADC(7, c7)

        float4 e0 = x4[(long long)c0.x * 32 + lane];
        float4 e1 = x4[(long long)c1.x * 32 + lane];
        float4 e2 = x4[(long long)c2.x * 32 + lane];
        float4 e3 = x4[(long long)c3.x * 32 + lane];
        float4 e4 = x4[(long long)c4.x * 32 + lane];
        float4 e5 = x4[(long long)c5.x * 32 + lane];
        float4 e6 = x4[(long long)c6.x * 32 + lane];
        float4 e7 = x4[(long long)c7.x * 32 + lane];

        float n0 = __int_as_float(c0.y), n1 = __int_as_float(c1.y);
        float n2 = __int_as_float(c2.y), n3 = __int_as_float(c3.y);
        float n4 = __int_as_float(c4.y), n5 = __int_as_float(c5.y);
        float n6 = __int_as_float(c6.y), n7 = __int_as_float(c7.y);

        acc.x += n0*e0.x + n1*e1.x + n2*e2.x + n3*e3.x
               + n4*e4.x + n5*e5.x + n6*e6.x + n7*e7.x;
        acc.y += n0*e0.y + n1*e1.y + n2*e2.y + n3*e3.y
               + n4*e4.y + n5*e5.y + n6*e6.y + n7*e7.y;
        acc.z += n0*e0.z + n1*e1.z + n2*e2.z + n3*e3.z
               + n4*e4.z + n5*e5.z + n6*e6.z + n7*e7.z;
        acc.w += n0*e0.w + n1*e1.w + n2*e2.w + n3*e3.w
               + n4*e4.w + n5*e5.w + n6*e6.w + n7*e7.w;
    }

    ((float4*)out)[(long long)d * 32 + lane] = acc;
}

// ---------------- warm-pattern gather probe (ncu slot 3) -------------------
// Same loop body as k_agg128 but indices from an integer hash -> identical
// random-gather memory pattern with NO dependence on CSR state, so even the
// cold first call (which ncu captures) is representative. Writes scratch.
__global__ void __launch_bounds__(256, 3)
k_probe(const float* __restrict__ xin, float* __restrict__ out) {
    int d = (blockIdx.x * blockDim.x + threadIdx.x) >> 5;
    int lane = threadIdx.x & 31;
    if (d >= PROBE_N) return;

    const float4* x4 = (const float4*)xin;
    float4 acc = make_float4(0.f, 0.f, 0.f, 0.f);

#pragma unroll
    for (int g = 0; g < 2; g++) {
        unsigned base = (unsigned)d * 2654435761u + (unsigned)g * 40503u;
        int s0 = (int)(((unsigned long long)((base + 1u) * 2246822519u) * N_NODES) >> 32);
        int s1 = (int)(((unsigned long long)((base + 2u) * 2246822519u) * N_NODES) >> 32);
        int s2 = (int)(((unsigned long long)((base + 3u) * 2246822519u) * N_NODES) >> 32);
        int s3 = (int)(((unsigned long long)((base + 4u) * 2246822519u) * N_NODES) >> 32);
        int s4 = (int)(((unsigned long long)((base + 5u) * 2246822519u) * N_NODES) >> 32);
        int s5 = (int)(((unsigned long long)((base + 6u) * 2246822519u) * N_NODES) >> 32);
        int s6 = (int)(((unsigned long long)((base + 7u) * 2246822519u) * N_NODES) >> 32);
        int s7 = (int)(((unsigned long long)((base + 8u) * 2246822519u) * N_NODES) >> 32);

        float4 e0 = x4[(long long)s0 * 32 + lane];
        float4 e1 = x4[(long long)s1 * 32 + lane];
        float4 e2 = x4[(long long)s2 * 32 + lane];
        float4 e3 = x4[(long long)s3 * 32 + lane];
        float4 e4 = x4[(long long)s4 * 32 + lane];
        float4 e5 = x4[(long long)s5 * 32 + lane];
        float4 e6 = x4[(long long)s6 * 32 + lane];
        float4 e7 = x4[(long long)s7 * 32 + lane];

        const float n = 0.0625f;
        acc.x += n * (e0.x + e1.x + e2.x + e3.x + e4.x + e5.x + e6.x + e7.x);
        acc.y += n * (e0.y + e1.y + e2.y + e3.y + e4.y + e5.y + e6.y + e7.y);
        acc.z += n * (e0.z + e1.z + e2.z + e3.z + e4.z + e5.z + e6.z + e7.z);
        acc.w += n * (e0.w + e1.w + e2.w + e3.w + e4.w + e5.w + e6.w + e7.w);
    }

    ((float4*)out)[(long long)d * 32 + lane] = acc;
}

// ---------------- dense GEMM + bias + relu: out = relu(X@W + b) -----------
template <int C>
__global__ void __launch_bounds__(256) k_gemm(const float* __restrict__ X,
                                              const float* __restrict__ W,
                                              const float* __restrict__ b,
                                              float* __restrict__ out) {
    __shared__ float Ws[128 * 64];
    __shared__ float Xt[128 * 32];

    const int col0 = blockIdx.y * 64;
    float4* Ws4 = (float4*)Ws;

    for (int i = threadIdx.x; i < 128 * 16; i += 256) {
        int k = i >> 4, t = i & 15;
        Ws4[i] = ((const float4*)(W + (long long)k * C + col0))[t];
    }

    const int tx = threadIdx.x & 15;
    const int ty = threadIdx.x >> 4;
    float4 bias = *(const float4*)(b + col0 + tx * 4);
    __syncthreads();

    const int ntiles = (N_NODES + 31) / 32;

    for (int tile = blockIdx.x; tile < ntiles; tile += gridDim.x) {
        int row0 = tile * 32;
        for (int i = threadIdx.x; i < 32 * 128; i += 256) {
            int r = i & 31, c = i >> 5;
            int row = row0 + r;
            Xt[c * 32 + r] = (row < N_NODES) ? X[(long long)row * 128 + c] : 0.f;
        }
        __syncthreads();

        float4 a0 = make_float4(0.f, 0.f, 0.f, 0.f);
        float4 a1 = make_float4(0.f, 0.f, 0.f, 0.f);

#pragma unroll 4
        for (int k = 0; k < 128; k++) {
            float4 w = Ws4[k * 16 + tx];
            float x0 = Xt[k * 32 + ty];
            float x1 = Xt[k * 32 + ty + 16];
            a0.x += x0 * w.x; a0.y += x0 * w.y; a0.z += x0 * w.z; a0.w += x0 * w.w;
            a1.x += x1 * w.x; a1.y += x1 * w.y; a1.z += x1 * w.z; a1.w += x1 * w.w;
        }

        a0.x = fmaxf(a0.x + bias.x, 0.f); a0.y = fmaxf(a0.y + bias.y, 0.f);
        a0.z = fmaxf(a0.z + bias.z, 0.f); a0.w = fmaxf(a0.w + bias.w, 0.f);
        a1.x = fmaxf(a1.x + bias.x, 0.f); a1.y = fmaxf(a1.y + bias.y, 0.f);
        a1.z = fmaxf(a1.z + bias.z, 0.f); a1.w = fmaxf(a1.w + bias.w, 0.f);

        int r0 = row0 + ty;
        int r1 = row0 + ty + 16;
        if (r0 < N_NODES)
            *(float4*)(out + (long long)r0 * C + col0 + tx * 4) = a0;
        if (r1 < N_NODES)
            *(float4*)(out + (long long)r1 * C + col0 + tx * 4) = a1;
        __syncthreads();
    }
}

// ---------------- attention pooling ----------------
__global__ void k_logits(const float* __restrict__ emb,
                         const float* __restrict__ Wa,
                         const float* __restrict__ ba) {
    __shared__ float smax[8];
    int lane = threadIdx.x & 31;
    int wid = threadIdx.x >> 5;
    int d = blockIdx.x * 8 + wid;

    const float4* e4 = (const float4*)(emb + (long long)d * C2);
    const float4* w4 = (const float4*)Wa;
    float s = 0.f;
#pragma unroll
    for (int j = 0; j < 2; j++) {
        float4 e = e4[lane + 32 * j];
        float4 w = w4[lane + 32 * j];
        s += e.x * w.x + e.y * w.y + e.z * w.z + e.w * w.w;
    }
#pragma unroll
    for (int o = 16; o > 0; o >>= 1) s += __shfl_xor_sync(0xffffffffu, s, o);
    float l = s + ba[0];
    if (lane == 0) { g_logits[d] = l; smax[wid] = l; }
    __syncthreads();
    if (threadIdx.x == 0) {
        float m = smax[0];
#pragma unroll
        for (int i = 1; i < 8; i++) m = fmaxf(m, smax[i]);
        atomicMax(&g_maxkey, enc_f(m));
    }
}

__global__ void k_exp(float* gout) {
    __shared__ float sh[256];
    int t = threadIdx.x;
    int i = blockIdx.x * 256 + t;
    if (blockIdx.x == 0) gout[t] = 0.f;
    float m = dec_f(g_maxkey);
    float p = 0.f;
    if (i < N_NODES) {
        p = expf(g_logits[i] - m);
        g_pw[i] = p;
    }
    sh[t] = p;
    __syncthreads();
    for (int off = 128; off > 0; off >>= 1) {
        if (t < off) sh[t] += sh[t + off];
        __syncthreads();
    }
    if (t == 0) atomicAdd(&g_sumexp, sh[0]);
}

__global__ void k_graph(const float* __restrict__ emb, float* __restrict__ gout) {
    int c = threadIdx.x;
    float acc = 0.f;
    for (int i = blockIdx.x; i < N_NODES; i += gridDim.x)
        acc += emb[(long long)i * C2 + c] * g_pw[i];
    atomicAdd(&gout[c], acc);
}

__global__ void k_scale(float* gout) {
    gout[threadIdx.x] *= (1.0f / g_sumexp);
}

// ---------------- launcher ----------------
extern "C" void kernel_launch(void* const* d_in, const int* in_sizes, int n_in,
                              void* d_out, int out_size) {
    const float* x  = (const float*)d_in[0];
    const void*  ei = d_in[1];
    const float* W1 = (const float*)d_in[2];
    const float* b1 = (const float*)d_in[3];
    const float* W2 = (const float*)d_in[4];
    const float* b2 = (const float*)d_in[5];
    const float* Wa = (const float*)d_in[6];
    const float* ba = (const float*)d_in[7];

    float* emb  = (float*)d_out;                              // (N, 256)
    float* gout = (float*)d_out + (long long)N_NODES * C2;    // (1, 256)

    k_sniff_init<<<NB_N, 256>>>(ei);                           // 0
    k_count<<<NB_E, 256>>>(ei);                                // 1
    k_scan1<<<NB_N, 256>>>();                                  // 2
    // PROBE at the ncu-profiled slot: synthetic-index clone of the hot
    // gather loop (no CSR dependency -> representative even on cold call).
    k_probe<<<(PROBE_N * 32 + 255) / 256, 256>>>(x, g_dbg);    // 3 <- profiled
    k_scan2<<<1, 256>>>();                                     // 4
    k_scan3<<<NB_N, 256>>>();                                  // 5
    k_scatter<<<NB_E, 256>>>(ei);                              // 6
    k_agg128<<<(N_NODES + 7) / 8, 256>>>(x, g_aggx, N_NODES);  // 7: S·X
    k_gemm<C1><<<dim3(296, 2), 256>>>(g_aggx, W1, b1, g_h1);   // 8
    k_agg128<<<(N_NODES + 7) / 8, 256>>>(g_h1, g_aggh, N_NODES); // 9: S·h
    k_gemm<C2><<<dim3(148, 4), 256>>>(g_aggh, W2, b2, emb);    // 10
    k_logits<<<N_NODES / 8, 256>>>(emb, Wa, ba);               // 11
    k_exp<<<NB_N, 256>>>(gout);                                // 12
    k_graph<<<512, 256>>>(emb, gout);                          // 13
    k_scale<<<1, 256>>>(gout);                                 // 14
}

// round 10
// speedup vs baseline: 1.0120x; 1.0120x over previous
#include <cuda_runtime.h>
#include <cuda_bf16.h>

#define N_NODES 50000
#define N_EDGES 800000
#define N_PAD   1150016                 // >= N_EDGES + 7*N_NODES, mult of 8
#define C1 128
#define C2 256
#define NB_N ((N_NODES + 255) / 256)   // 196
#define NB_E ((N_EDGES + 255) / 256)   // 3125
#define NB_P ((N_PAD + 255) / 256)

// ---------------- device scratch (static, no allocation) ----------------
__device__ int      g_is64;
__device__ int      g_degi[N_NODES];
__device__ float    g_dinv[N_NODES];
__device__ int      g_rowoff[N_NODES + 1];   // padded-CSR offsets (mult of 8)
__device__ int      g_cursor[N_NODES];
__device__ int      g_partial[256];
__device__ int4     g_csr4[N_PAD / 2];       // int2 pairs {src, nrm-bits}
__device__ float    g_aggx[(long long)N_NODES * C1];  // S·X
__device__ float    g_h1[(long long)N_NODES * C1];    // relu(aggx·W1+b1)
__device__ float    g_aggh[(long long)N_NODES * C1];  // S·h1
__device__ float    g_logits[N_NODES];
__device__ float    g_pw[N_NODES];
__device__ unsigned g_maxkey;
__device__ float    g_sumexp;

// ---------------- helpers ----------------
__device__ __forceinline__ int edge_idx(const void* ei, long long i, int is64) {
    if (is64) return (int)((const long long*)ei)[i];
    return ((const int*)ei)[i];
}
__device__ __forceinline__ unsigned enc_f(float f) {
    unsigned u = __float_as_uint(f);
    return (u & 0x80000000u) ? ~u : (u | 0x80000000u);
}
__device__ __forceinline__ float dec_f(unsigned k) {
    unsigned u = (k & 0x80000000u) ? (k ^ 0x80000000u) : ~k;
    return __uint_as_float(u);
}

// ---------------- preprocessing ----------------
// launch 0: zero degi + zero the padded CSR (padding entries must be
// {src=0, nrm=0}); thread 0 sniffs edge dtype (int64 vs int32).
__global__ void k_sniff_init(const void* ei) {
    int i = blockIdx.x * blockDim.x + threadIdx.x;
    if (i < N_NODES) g_degi[i] = 0;
    if (i < N_PAD / 2) g_csr4[i] = make_int4(0, 0, 0, 0);
    if (i == 0) {
        g_maxkey = 0u; g_sumexp = 0.f;
        const long long* p = (const long long*)ei;
        int ok = 1;
        for (int q = 0; q < 64; q++) {
            long long v = p[q];
            if (v < 0 || v >= N_NODES) { ok = 0; break; }
        }
        g_is64 = ok;
    }
}

__global__ void k_count(const void* ei) {
    int e = blockIdx.x * blockDim.x + threadIdx.x;
    if (e >= N_EDGES) return;
    int d = edge_idx(ei, (long long)N_EDGES + e, g_is64);
    atomicAdd(&g_degi[d], 1);
}

// per-block inclusive scan of PADDED degrees (ceil8) + dinv from real degree
__global__ void k_scan1() {
    __shared__ int sh[256];
    int t = threadIdx.x;
    int i = blockIdx.x * 256 + t;
    int v = (i < N_NODES) ? g_degi[i] : 0;
    if (i < N_NODES) g_dinv[i] = rsqrtf((float)(v + 1)); // +1 self loop
    int vp = (v + 7) & ~7;
    sh[t] = vp;
    __syncthreads();
    for (int off = 1; off < 256; off <<= 1) {
        int add = (t >= off) ? sh[t - off] : 0;
        __syncthreads();
        sh[t] += add;
        __syncthreads();
    }
    if (i < N_NODES) g_rowoff[i + 1] = sh[t];
    if (t == 255) g_partial[blockIdx.x] = sh[255];
}

__global__ void k_scan2() {
    __shared__ int sh[256];
    int t = threadIdx.x;
    int v = (t < NB_N) ? g_partial[t] : 0;
    sh[t] = v;
    __syncthreads();
    for (int off = 1; off < 256; off <<= 1) {
        int add = (t >= off) ? sh[t - off] : 0;
        __syncthreads();
        sh[t] += add;
        __syncthreads();
    }
    g_partial[t] = sh[t] - v; // exclusive
}

// final rowoff + cursor init (fused)
__global__ void k_scan3() {
    int i = blockIdx.x * blockDim.x + threadIdx.x;
    if (i == 0) { g_rowoff[0] = 0; g_cursor[0] = 0; }
    if (i < N_NODES) {
        int r = g_rowoff[i + 1] + g_partial[i >> 8];
        g_rowoff[i + 1] = r;
        if (i + 1 < N_NODES) g_cursor[i + 1] = r;
    }
}

__global__ void k_scatter(const void* ei) {
    int e = blockIdx.x * blockDim.x + threadIdx.x;
    if (e >= N_EDGES) return;
    int is64 = g_is64;
    int s = edge_idx(ei, e, is64);
    int d = edge_idx(ei, (long long)N_EDGES + e, is64);
    int pos = atomicAdd(&g_cursor[d], 1);
    ((int2*)g_csr4)[pos] = make_int2(s, __float_as_int(g_dinv[s] * g_dinv[d]));
}

// ---------------- aggregation: out = S · x  (128-dim, warp per node) ------
// out[d] = dinv[d]^2 * x[d] + sum_edges nrm * x[src]
// Padded CSR: the per-node range is an exact multiple of 8, padding entries
// are {0, 0.0f} (harmless cached gather * 0). Loop body has NO bounds logic:
// 4 uniform LDG.128 index loads + 8 independent 512B gathers in flight.
__global__ void __launch_bounds__(256, 3)
k_agg128(const float* __restrict__ xin, float* __restrict__ out, int nlimit) {
    int d = (blockIdx.x * blockDim.x + threadIdx.x) >> 5;
    int lane = threadIdx.x & 31;
    if (d >= nlimit) return;

    const float4* x4 = (const float4*)xin;

    float di = g_dinv[d];
    float sl = di * di;

    float4 v0 = x4[(long long)d * 32 + lane];
    float4 acc;
    acc.x = sl * v0.x; acc.y = sl * v0.y; acc.z = sl * v0.z; acc.w = sl * v0.w;

    int j = g_rowoff[d] >> 1;        // index into int4 pairs
    int end = g_rowoff[d + 1] >> 1;

    for (; j < end; j += 4) {
        int4 p01 = g_csr4[j + 0];
        int4 p23 = g_csr4[j + 1];
        int4 p45 = g_csr4[j + 2];
        int4 p67 = g_csr4[j + 3];

        float4 e0 = x4[(long long)p01.x * 32 + lane];
        float4 e1 = x4[(long long)p01.z * 32 + lane];
        float4 e2 = x4[(long long)p23.x * 32 + lane];
        float4 e3 = x4[(long long)p23.z * 32 + lane];
        float4 e4 = x4[(long long)p45.x * 32 + lane];
        float4 e5 = x4[(long long)p45.z * 32 + lane];
        float4 e6 = x4[(long long)p67.x * 32 + lane];
        float4 e7 = x4[(long long)p67.z * 32 + lane];

        float n0 = __int_as_float(p01.y), n1 = __int_as_float(p01.w);
        float n2 = __int_as_float(p23.y), n3 = __int_as_float(p23.w);
        float n4 = __int_as_float(p45.y), n5 = __int_as_float(p45.w);
        float n6 = __int_as_float(p67.y), n7 = __int_as_float(p67.w);

        acc.x += n0*e0.x + n1*e1.x + n2*e2.x + n3*e3.x
               + n4*e4.x + n5*e5.x + n6*e6.x + n7*e7.x;
        acc.y += n0*e0.y + n1*e1.y + n2*e2.y + n3*e3.y
               + n4*e4.y + n5*e5.y + n6*e6.y + n7*e7.y;
        acc.z += n0*e0.z + n1*e1.z + n2*e2.z + n3*e3.z
               + n4*e4.z + n5*e5.z + n6*e6.z + n7*e7.z;
        acc.w += n0*e0.w + n1*e1.w + n2*e2.w + n3*e3.w
               + n4*e4.w + n5*e5.w + n6*e6.w + n7*e7.w;
    }

    ((float4*)out)[(long long)d * 32 + lane] = acc;
}

// ---------------- dense GEMM + bias + relu: out = relu(X@W + b) -----------
// Threads own adjacent rows (2ty, 2ty+1): X smem read is one LDS.64 ->
// 3 smem wavefronts per warp-k instead of 4.
template <int C>
__global__ void __launch_bounds__(256) k_gemm(const float* __restrict__ X,
                                              const float* __restrict__ W,
                                              const float* __restrict__ b,
                                              float* __restrict__ out) {
    __shared__ float Ws[128 * 64];
    __shared__ float Xt[128 * 32];

    const int col0 = blockIdx.y * 64;
    float4* Ws4 = (float4*)Ws;

    for (int i = threadIdx.x; i < 128 * 16; i += 256) {
        int k = i >> 4, t = i & 15;
        Ws4[i] = ((const float4*)(W + (long long)k * C + col0))[t];
    }

    const int tx = threadIdx.x & 15;
    const int ty = threadIdx.x >> 4;
    float4 bias = *(const float4*)(b + col0 + tx * 4);
    __syncthreads();

    const int ntiles = (N_NODES + 31) / 32;

    for (int tile = blockIdx.x; tile < ntiles; tile += gridDim.x) {
        int row0 = tile * 32;
        for (int i = threadIdx.x; i < 32 * 128; i += 256) {
            int r = i & 31, c = i >> 5;
            int row = row0 + r;
            Xt[c * 32 + r] = (row < N_NODES) ? X[(long long)row * 128 + c] : 0.f;
        }
        __syncthreads();

        float4 a0 = make_float4(0.f, 0.f, 0.f, 0.f);
        float4 a1 = make_float4(0.f, 0.f, 0.f, 0.f);

#pragma unroll 4
        for (int k = 0; k < 128; k++) {
            float4 w = Ws4[k * 16 + tx];
            float2 xp = *(const float2*)&Xt[k * 32 + 2 * ty];
            a0.x += xp.x * w.x; a0.y += xp.x * w.y;
            a0.z += xp.x * w.z; a0.w += xp.x * w.w;
            a1.x += xp.y * w.x; a1.y += xp.y * w.y;
            a1.z += xp.y * w.z; a1.w += xp.y * w.w;
        }

        a0.x = fmaxf(a0.x + bias.x, 0.f); a0.y = fmaxf(a0.y + bias.y, 0.f);
        a0.z = fmaxf(a0.z + bias.z, 0.f); a0.w = fmaxf(a0.w + bias.w, 0.f);
        a1.x = fmaxf(a1.x + bias.x, 0.f); a1.y = fmaxf(a1.y + bias.y, 0.f);
        a1.z = fmaxf(a1.z + bias.z, 0.f); a1.w = fmaxf(a1.w + bias.w, 0.f);

        int r0 = row0 + 2 * ty;
        int r1 = row0 + 2 * ty + 1;
        if (r0 < N_NODES)
            *(float4*)(out + (long long)r0 * C + col0 + tx * 4) = a0;
        if (r1 < N_NODES)
            *(float4*)(out + (long long)r1 * C + col0 + tx * 4) = a1;
        __syncthreads();
    }
}

// ---------------- attention pooling ----------------
__global__ void k_logits(const float* __restrict__ emb,
                         const float* __restrict__ Wa,
                         const float* __restrict__ ba) {
    __shared__ float smax[8];
    int lane = threadIdx.x & 31;
    int wid = threadIdx.x >> 5;
    int d = blockIdx.x * 8 + wid;

    const float4* e4 = (const float4*)(emb + (long long)d * C2);
    const float4* w4 = (const float4*)Wa;
    float s = 0.f;
#pragma unroll
    for (int j = 0; j < 2; j++) {
        float4 e = e4[lane + 32 * j];
        float4 w = w4[lane + 32 * j];
        s += e.x * w.x + e.y * w.y + e.z * w.z + e.w * w.w;
    }
#pragma unroll
    for (int o = 16; o > 0; o >>= 1) s += __shfl_xor_sync(0xffffffffu, s, o);
    float l = s + ba[0];
    if (lane == 0) { g_logits[d] = l; smax[wid] = l; }
    __syncthreads();
    if (threadIdx.x == 0) {
        float m = smax[0];
#pragma unroll
        for (int i = 1; i < 8; i++) m = fmaxf(m, smax[i]);
        atomicMax(&g_maxkey, enc_f(m));
    }
}

__global__ void k_exp(float* gout) {
    __shared__ float sh[256];
    int t = threadIdx.x;
    int i = blockIdx.x * 256 + t;
    if (blockIdx.x == 0) gout[t] = 0.f;
    float m = dec_f(g_maxkey);
    float p = 0.f;
    if (i < N_NODES) {
        p = expf(g_logits[i] - m);
        g_pw[i] = p;
    }
    sh[t] = p;
    __syncthreads();
    for (int off = 128; off > 0; off >>= 1) {
        if (t < off) sh[t] += sh[t + off];
        __syncthreads();
    }
    if (t == 0) atomicAdd(&g_sumexp, sh[0]);
}

__global__ void k_graph(const float* __restrict__ emb, float* __restrict__ gout) {
    int c = threadIdx.x;
    float acc = 0.f;
    for (int i = blockIdx.x; i < N_NODES; i += gridDim.x)
        acc += emb[(long long)i * C2 + c] * g_pw[i];
    atomicAdd(&gout[c], acc);
}

__global__ void k_scale(float* gout) {
    gout[threadIdx.x] *= (1.0f / g_sumexp);
}

// ---------------- launcher ----------------
extern "C" void kernel_launch(void* const* d_in, const int* in_sizes, int n_in,
                              void* d_out, int out_size) {
    const float* x  = (const float*)d_in[0];
    const void*  ei = d_in[1];
    const float* W1 = (const float*)d_in[2];
    const float* b1 = (const float*)d_in[3];
    const float* W2 = (const float*)d_in[4];
    const float* b2 = (const float*)d_in[5];
    const float* Wa = (const float*)d_in[6];
    const float* ba = (const float*)d_in[7];

    float* emb  = (float*)d_out;                              // (N, 256)
    float* gout = (float*)d_out + (long long)N_NODES * C2;    // (1, 256)

    k_sniff_init<<<NB_P, 256>>>(ei);                           // 0
    k_count<<<NB_E, 256>>>(ei);                                // 1
    k_scan1<<<NB_N, 256>>>();                                  // 2
    // MEASUREMENT: duplicate of pass 7 (idempotent; overwritten after
    // scatter on the cold call). Its dur_us delta = true per-pass agg cost.
    k_agg128<<<(N_NODES + 7) / 8, 256>>>(x, g_aggx, N_NODES);  // 3 <- profiled
    k_scan2<<<1, 256>>>();                                     // 4
    k_scan3<<<NB_N, 256>>>();                                  // 5
    k_scatter<<<NB_E, 256>>>(ei);                              // 6
    k_agg128<<<(N_NODES + 7) / 8, 256>>>(x, g_aggx, N_NODES);  // 7: S·X
    k_gemm<C1><<<dim3(296, 2), 256>>>(g_aggx, W1, b1, g_h1);   // 8
    k_agg128<<<(N_NODES + 7) / 8, 256>>>(g_h1, g_aggh, N_NODES); // 9: S·h
    k_gemm<C2><<<dim3(148, 4), 256>>>(g_aggh, W2, b2, emb);    // 10
    k_logits<<<N_NODES / 8, 256>>>(emb, Wa, ba);               // 11
    k_exp<<<NB_N, 256>>>(gout);                                // 12
    k_graph<<<512, 256>>>(emb, gout);                          // 13
    k_scale<<<1, 256>>>(gout);                                 // 14
}

// round 11
// speedup vs baseline: 1.0367x; 1.0244x over previous
#include <cuda_runtime.h>
#include <cuda_bf16.h>

#define N_NODES 50000
#define N_EDGES 800000
#define N_PAD   1150016                 // >= N_EDGES + 7*N_NODES, mult of 8
#define C1 128
#define C2 256
#define NB_N ((N_NODES + 255) / 256)   // 196
#define NB_E ((N_EDGES + 255) / 256)   // 3125
#define NB_P ((N_PAD + 255) / 256)

// ---------------- device scratch (static, no allocation) ----------------
__device__ int      g_is64;
__device__ int      g_degi[N_NODES];
__device__ float    g_dinv[N_NODES];
__device__ int      g_rowoff[N_NODES + 1];   // padded-CSR offsets (mult of 8)
__device__ int      g_cursor[N_NODES];
__device__ int      g_partial[256];
__device__ int2     g_csr2[N_PAD];           // {src, float_as_int(nrm)}
__device__ float    g_aggx[(long long)N_NODES * C1];  // S·X
__device__ float    g_h1[(long long)N_NODES * C1];    // relu(aggx·W1+b1)
__device__ float    g_aggh[(long long)N_NODES * C1];  // S·h1
__device__ float    g_logits[N_NODES];
__device__ float    g_pw[N_NODES];
__device__ unsigned g_maxkey;
__device__ float    g_sumexp;

// ---------------- helpers ----------------
__device__ __forceinline__ int edge_idx(const void* ei, long long i, int is64) {
    if (is64) return (int)((const long long*)ei)[i];
    return ((const int*)ei)[i];
}
__device__ __forceinline__ unsigned enc_f(float f) {
    unsigned u = __float_as_uint(f);
    return (u & 0x80000000u) ? ~u : (u | 0x80000000u);
}
__device__ __forceinline__ float dec_f(unsigned k) {
    unsigned u = (k & 0x80000000u) ? (k ^ 0x80000000u) : ~k;
    return __uint_as_float(u);
}

// ---------------- preprocessing ----------------
// launch 0: zero degi + zero the padded CSR (padding entries must be
// {src=0, nrm=0}); thread 0 sniffs edge dtype (int64 vs int32).
__global__ void k_sniff_init(const void* ei) {
    int i = blockIdx.x * blockDim.x + threadIdx.x;
    if (i < N_NODES) g_degi[i] = 0;
    if (i < N_PAD / 2) ((int4*)g_csr2)[i] = make_int4(0, 0, 0, 0);
    if (i == 0) {
        g_maxkey = 0u; g_sumexp = 0.f;
        const long long* p = (const long long*)ei;
        int ok = 1;
        for (int q = 0; q < 64; q++) {
            long long v = p[q];
            if (v < 0 || v >= N_NODES) { ok = 0; break; }
        }
        g_is64 = ok;
    }
}

__global__ void k_count(const void* ei) {
    int e = blockIdx.x * blockDim.x + threadIdx.x;
    if (e >= N_EDGES) return;
    int d = edge_idx(ei, (long long)N_EDGES + e, g_is64);
    atomicAdd(&g_degi[d], 1);
}

// per-block inclusive scan of PADDED degrees (ceil8) + dinv from real degree
__global__ void k_scan1() {
    __shared__ int sh[256];
    int t = threadIdx.x;
    int i = blockIdx.x * 256 + t;
    int v = (i < N_NODES) ? g_degi[i] : 0;
    if (i < N_NODES) g_dinv[i] = rsqrtf((float)(v + 1)); // +1 self loop
    int vp = (v + 7) & ~7;
    sh[t] = vp;
    __syncthreads();
    for (int off = 1; off < 256; off <<= 1) {
        int add = (t >= off) ? sh[t - off] : 0;
        __syncthreads();
        sh[t] += add;
        __syncthreads();
    }
    if (i < N_NODES) g_rowoff[i + 1] = sh[t];
    if (t == 255) g_partial[blockIdx.x] = sh[255];
}

__global__ void k_scan2() {
    __shared__ int sh[256];
    int t = threadIdx.x;
    int v = (t < NB_N) ? g_partial[t] : 0;
    sh[t] = v;
    __syncthreads();
    for (int off = 1; off < 256; off <<= 1) {
        int add = (t >= off) ? sh[t - off] : 0;
        __syncthreads();
        sh[t] += add;
        __syncthreads();
    }
    g_partial[t] = sh[t] - v; // exclusive
}

// final rowoff + cursor init (fused)
__global__ void k_scan3() {
    int i = blockIdx.x * blockDim.x + threadIdx.x;
    if (i == 0) { g_rowoff[0] = 0; g_cursor[0] = 0; }
    if (i < N_NODES) {
        int r = g_rowoff[i + 1] + g_partial[i >> 8];
        g_rowoff[i + 1] = r;
        if (i + 1 < N_NODES) g_cursor[i + 1] = r;
    }
}

__global__ void k_scatter(const void* ei) {
    int e = blockIdx.x * blockDim.x + threadIdx.x;
    if (e >= N_EDGES) return;
    int is64 = g_is64;
    int s = edge_idx(ei, e, is64);
    int d = edge_idx(ei, (long long)N_EDGES + e, is64);
    int pos = atomicAdd(&g_cursor[d], 1);
    g_csr2[pos] = make_int2(s, __float_as_int(g_dinv[s] * g_dinv[d]));
}

// ---------------- aggregation: out = S · x  (128-dim, warp per node) ------
// out[d] = dinv[d]^2 * x[d] + sum_edges nrm * x[src]
// CSR-vector with shuffle-staged indices: each lane loads ONE csr entry of
// the node's segment (single coalesced LDG -> one scoreboard wait per 32
// edges), then src/nrm are broadcast via shfl (register pipe, no long
// scoreboard). Gather groups of 8 issue with no per-iteration index load.
// Segments are padded to mult of 8 with {0, 0.0f} -> inner loop mask-free.
__global__ void __launch_bounds__(256, 3)
k_agg128(const float* __restrict__ xin, float* __restrict__ out, int nlimit) {
    int d = (blockIdx.x * blockDim.x + threadIdx.x) >> 5;
    int lane = threadIdx.x & 31;
    if (d >= nlimit) return;

    const float4* x4 = (const float4*)xin;

    float di = g_dinv[d];
    float sl = di * di;

    float4 v0 = x4[(long long)d * 32 + lane];
    float4 acc;
    acc.x = sl * v0.x; acc.y = sl * v0.y; acc.z = sl * v0.z; acc.w = sl * v0.w;

    int j = g_rowoff[d];
    int end = g_rowoff[d + 1];

    for (int base = j; base < end; base += 32) {
        int idx = base + lane;
        int2 c = make_int2(0, 0);
        if (idx < end) c = g_csr2[idx];
        int cnt = end - base; cnt = (cnt > 32) ? 32 : cnt;  // multiple of 8

        for (int qq = 0; qq < cnt; qq += 8) {
            int s0 = __shfl_sync(0xffffffffu, c.x, qq + 0);
            int s1 = __shfl_sync(0xffffffffu, c.x, qq + 1);
            int s2 = __shfl_sync(0xffffffffu, c.x, qq + 2);
            int s3 = __shfl_sync(0xffffffffu, c.x, qq + 3);
            int s4 = __shfl_sync(0xffffffffu, c.x, qq + 4);
            int s5 = __shfl_sync(0xffffffffu, c.x, qq + 5);
            int s6 = __shfl_sync(0xffffffffu, c.x, qq + 6);
            int s7 = __shfl_sync(0xffffffffu, c.x, qq + 7);

            float4 e0 = x4[(long long)s0 * 32 + lane];
            float4 e1 = x4[(long long)s1 * 32 + lane];
            float4 e2 = x4[(long long)s2 * 32 + lane];
            float4 e3 = x4[(long long)s3 * 32 + lane];
            float4 e4 = x4[(long long)s4 * 32 + lane];
            float4 e5 = x4[(long long)s5 * 32 + lane];
            float4 e6 = x4[(long long)s6 * 32 + lane];
            float4 e7 = x4[(long long)s7 * 32 + lane];

            float n0 = __uint_as_float(__shfl_sync(0xffffffffu, c.y, qq + 0));
            float n1 = __uint_as_float(__shfl_sync(0xffffffffu, c.y, qq + 1));
            float n2 = __uint_as_float(__shfl_sync(0xffffffffu, c.y, qq + 2));
            float n3 = __uint_as_float(__shfl_sync(0xffffffffu, c.y, qq + 3));
            float n4 = __uint_as_float(__shfl_sync(0xffffffffu, c.y, qq + 4));
            float n5 = __uint_as_float(__shfl_sync(0xffffffffu, c.y, qq + 5));
            float n6 = __uint_as_float(__shfl_sync(0xffffffffu, c.y, qq + 6));
            float n7 = __uint_as_float(__shfl_sync(0xffffffffu, c.y, qq + 7));

            acc.x += n0*e0.x + n1*e1.x + n2*e2.x + n3*e3.x
                   + n4*e4.x + n5*e5.x + n6*e6.x + n7*e7.x;
            acc.y += n0*e0.y + n1*e1.y + n2*e2.y + n3*e3.y
                   + n4*e4.y + n5*e5.y + n6*e6.y + n7*e7.y;
            acc.z += n0*e0.z + n1*e1.z + n2*e2.z + n3*e3.z
                   + n4*e4.z + n5*e5.z + n6*e6.z + n7*e7.z;
            acc.w += n0*e0.w + n1*e1.w + n2*e2.w + n3*e3.w
                   + n4*e4.w + n5*e5.w + n6*e6.w + n7*e7.w;
        }
    }

    ((float4*)out)[(long long)d * 32 + lane] = acc;
}

// ---------------- dense GEMM + bias + relu: out = relu(X@W + b) -----------
template <int C>
__global__ void __launch_bounds__(256) k_gemm(const float* __restrict__ X,
                                              const float* __restrict__ W,
                                              const float* __restrict__ b,
                                              float* __restrict__ out) {
    __shared__ float Ws[128 * 64];
    __shared__ float Xt[128 * 32];

    const int col0 = blockIdx.y * 64;
    float4* Ws4 = (float4*)Ws;

    for (int i = threadIdx.x; i < 128 * 16; i += 256) {
        int k = i >> 4, t = i & 15;
        Ws4[i] = ((const float4*)(W + (long long)k * C + col0))[t];
    }

    const int tx = threadIdx.x & 15;
    const int ty = threadIdx.x >> 4;
    float4 bias = *(const float4*)(b + col0 + tx * 4);
    __syncthreads();

    const int ntiles = (N_NODES + 31) / 32;

    for (int tile = blockIdx.x; tile < ntiles; tile += gridDim.x) {
        int row0 = tile * 32;
        for (int i = threadIdx.x; i < 32 * 128; i += 256) {
            int r = i & 31, c = i >> 5;
            int row = row0 + r;
            Xt[c * 32 + r] = (row < N_NODES) ? X[(long long)row * 128 + c] : 0.f;
        }
        __syncthreads();

        float4 a0 = make_float4(0.f, 0.f, 0.f, 0.f);
        float4 a1 = make_float4(0.f, 0.f, 0.f, 0.f);

#pragma unroll 4
        for (int k = 0; k < 128; k++) {
            float4 w = Ws4[k * 16 + tx];
            float2 xp = *(const float2*)&Xt[k * 32 + 2 * ty];
            a0.x += xp.x * w.x; a0.y += xp.x * w.y;
            a0.z += xp.x * w.z; a0.w += xp.x * w.w;
            a1.x += xp.y * w.x; a1.y += xp.y * w.y;
            a1.z += xp.y * w.z; a1.w += xp.y * w.w;
        }

        a0.x = fmaxf(a0.x + bias.x, 0.f); a0.y = fmaxf(a0.y + bias.y, 0.f);
        a0.z = fmaxf(a0.z + bias.z, 0.f); a0.w = fmaxf(a0.w + bias.w, 0.f);
        a1.x = fmaxf(a1.x + bias.x, 0.f); a1.y = fmaxf(a1.y + bias.y, 0.f);
        a1.z = fmaxf(a1.z + bias.z, 0.f); a1.w = fmaxf(a1.w + bias.w, 0.f);

        int r0 = row0 + 2 * ty;
        int r1 = row0 + 2 * ty + 1;
        if (r0 < N_NODES)
            *(float4*)(out + (long long)r0 * C + col0 + tx * 4) = a0;
        if (r1 < N_NODES)
            *(float4*)(out + (long long)r1 * C + col0 + tx * 4) = a1;
        __syncthreads();
    }
}

// ---------------- attention pooling ----------------
__global__ void k_logits(const float* __restrict__ emb,
                         const float* __restrict__ Wa,
                         const float* __restrict__ ba) {
    __shared__ float smax[8];
    int lane = threadIdx.x & 31;
    int wid = threadIdx.x >> 5;
    int d = blockIdx.x * 8 + wid;

    const float4* e4 = (const float4*)(emb + (long long)d * C2);
    const float4* w4 = (const float4*)Wa;
    float s = 0.f;
#pragma unroll
    for (int j = 0; j < 2; j++) {
        float4 e = e4[lane + 32 * j];
        float4 w = w4[lane + 32 * j];
        s += e.x * w.x + e.y * w.y + e.z * w.z + e.w * w.w;
    }
#pragma unroll
    for (int o = 16; o > 0; o >>= 1) s += __shfl_xor_sync(0xffffffffu, s, o);
    float l = s + ba[0];
    if (lane == 0) { g_logits[d] = l; smax[wid] = l; }
    __syncthreads();
    if (threadIdx.x == 0) {
        float m = smax[0];
#pragma unroll
        for (int i = 1; i < 8; i++) m = fmaxf(m, smax[i]);
        atomicMax(&g_maxkey, enc_f(m));
    }
}

__global__ void k_exp(float* gout) {
    __shared__ float sh[256];
    int t = threadIdx.x;
    int i = blockIdx.x * 256 + t;
    if (blockIdx.x == 0) gout[t] = 0.f;
    float m = dec_f(g_maxkey);
    float p = 0.f;
    if (i < N_NODES) {
        p = expf(g_logits[i] - m);
        g_pw[i] = p;
    }
    sh[t] = p;
    __syncthreads();
    for (int off = 128; off > 0; off >>= 1) {
        if (t < off) sh[t] += sh[t + off];
        __syncthreads();
    }
    if (t == 0) atomicAdd(&g_sumexp, sh[0]);
}

__global__ void k_graph(const float* __restrict__ emb, float* __restrict__ gout) {
    int c = threadIdx.x;
    float acc = 0.f;
    for (int i = blockIdx.x; i < N_NODES; i += gridDim.x)
        acc += emb[(long long)i * C2 + c] * g_pw[i];
    atomicAdd(&gout[c], acc);
}

__global__ void k_scale(float* gout) {
    gout[threadIdx.x] *= (1.0f / g_sumexp);
}

// ---------------- launcher ----------------
extern "C" void kernel_launch(void* const* d_in, const int* in_sizes, int n_in,
                              void* d_out, int out_size) {
    const float* x  = (const float*)d_in[0];
    const void*  ei = d_in[1];
    const float* W1 = (const float*)d_in[2];
    const float* b1 = (const float*)d_in[3];
    const float* W2 = (const float*)d_in[4];
    const float* b2 = (const float*)d_in[5];
    const float* Wa = (const float*)d_in[6];
    const float* ba = (const float*)d_in[7];

    float* emb  = (float*)d_out;                              // (N, 256)
    float* gout = (float*)d_out + (long long)N_NODES * C2;    // (1, 256)

    k_sniff_init<<<NB_P, 256>>>(ei);                           // 0
    k_count<<<NB_E, 256>>>(ei);                                // 1
    k_scan1<<<NB_N, 256>>>();                                  // 2
    k_agg128<<<(N_NODES + 7) / 8, 256>>>(x, g_aggx, N_NODES);  // 3 <- profiled
    k_scan2<<<1, 256>>>();                                     // 4
    k_scan3<<<NB_N, 256>>>();                                  // 5
    k_scatter<<<NB_E, 256>>>(ei);                              // 6
    k_agg128<<<(N_NODES + 7) / 8, 256>>>(x, g_aggx, N_NODES);  // 7: S·X (real)
    k_gemm<C1><<<dim3(296, 2), 256>>>(g_aggx, W1, b1, g_h1);   // 8
    k_agg128<<<(N_NODES + 7) / 8, 256>>>(g_h1, g_aggh, N_NODES); // 9: S·h
    k_gemm<C2><<<dim3(148, 4), 256>>>(g_aggh, W2, b2, emb);    // 10
    k_logits<<<N_NODES / 8, 256>>>(emb, Wa, ba);               // 11
    k_exp<<<NB_N, 256>>>(gout);                                // 12
    k_graph<<<512, 256>>>(emb, gout);                          // 13
    k_scale<<<1, 256>>>(gout);                                 // 14
}

// round 14
// speedup vs baseline: 1.0597x; 1.0222x over previous
#include <cuda_runtime.h>
#include <cuda_bf16.h>

#define N_NODES 50000
#define N_EDGES 800000
#define N_PAD   1150016                 // >= N_EDGES + 7*N_NODES, mult of 8
#define C1 128
#define C2 256
#define NB_N ((N_NODES + 255) / 256)   // 196
#define NB_E ((N_EDGES + 255) / 256)   // 3125
#define NB_P ((N_PAD + 255) / 256)
#define SEG_CAP 1024                   // smem csr buffer entries per block

// ---------------- device scratch (static, no allocation) ----------------
__device__ int      g_is64;
__device__ int      g_degi[N_NODES];
__device__ float    g_dinv[N_NODES];
__device__ int      g_rowoff[N_NODES + 1];   // padded-CSR offsets (mult of 8)
__device__ int      g_cursor[N_NODES];
__device__ int      g_partial[256];
__device__ int2     g_csr2[N_PAD];           // {src, float_as_int(nrm)}
__device__ float    g_aggx[(long long)N_NODES * C1];  // S·X
__device__ float    g_h1[(long long)N_NODES * C1];    // relu(aggx·W1+b1)
__device__ float    g_aggh[(long long)N_NODES * C1];  // S·h1
__device__ float    g_logits[N_NODES];
__device__ float    g_pw[N_NODES];
__device__ unsigned g_maxkey;
__device__ float    g_sumexp;

// ---------------- helpers ----------------
__device__ __forceinline__ int edge_idx(const void* ei, long long i, int is64) {
    if (is64) return (int)((const long long*)ei)[i];
    return ((const int*)ei)[i];
}
__device__ __forceinline__ unsigned enc_f(float f) {
    unsigned u = __float_as_uint(f);
    return (u & 0x80000000u) ? ~u : (u | 0x80000000u);
}
__device__ __forceinline__ float dec_f(unsigned k) {
    unsigned u = (k & 0x80000000u) ? (k ^ 0x80000000u) : ~k;
    return __uint_as_float(u);
}

// ---------------- preprocessing ----------------
// launch 0: zero degi + zero the padded CSR (padding entries must be
// {src=0, nrm=0}); thread 0 sniffs edge dtype (int64 vs int32).
__global__ void k_sniff_init(const void* ei) {
    int i = blockIdx.x * blockDim.x + threadIdx.x;
    if (i < N_NODES) g_degi[i] = 0;
    if (i < N_PAD / 2) ((int4*)g_csr2)[i] = make_int4(0, 0, 0, 0);
    if (i == 0) {
        g_maxkey = 0u; g_sumexp = 0.f;
        const long long* p = (const long long*)ei;
        int ok = 1;
        for (int q = 0; q < 64; q++) {
            long long v = p[q];
            if (v < 0 || v >= N_NODES) { ok = 0; break; }
        }
        g_is64 = ok;
    }
}

__global__ void k_count(const void* ei) {
    int e = blockIdx.x * blockDim.x + threadIdx.x;
    if (e >= N_EDGES) return;
    int d = edge_idx(ei, (long long)N_EDGES + e, g_is64);
    atomicAdd(&g_degi[d], 1);
}

// per-block inclusive scan of PADDED degrees (ceil8) + dinv from real degree
__global__ void k_scan1() {
    __shared__ int sh[256];
    int t = threadIdx.x;
    int i = blockIdx.x * 256 + t;
    int v = (i < N_NODES) ? g_degi[i] : 0;
    if (i < N_NODES) g_dinv[i] = rsqrtf((float)(v + 1)); // +1 self loop
    int vp = (v + 7) & ~7;
    sh[t] = vp;
    __syncthreads();
    for (int off = 1; off < 256; off <<= 1) {
        int add = (t >= off) ? sh[t - off] : 0;
        __syncthreads();
        sh[t] += add;
        __syncthreads();
    }
    if (i < N_NODES) g_rowoff[i + 1] = sh[t];
    if (t == 255) g_partial[blockIdx.x] = sh[255];
}

__global__ void k_scan2() {
    __shared__ int sh[256];
    int t = threadIdx.x;
    int v = (t < NB_N) ? g_partial[t] : 0;
    sh[t] = v;
    __syncthreads();
    for (int off = 1; off < 256; off <<= 1) {
        int add = (t >= off) ? sh[t - off] : 0;
        __syncthreads();
        sh[t] += add;
        __syncthreads();
    }
    g_partial[t] = sh[t] - v; // exclusive
}

// final rowoff + cursor init (fused)
__global__ void k_scan3() {
    int i = blockIdx.x * blockDim.x + threadIdx.x;
    if (i == 0) { g_rowoff[0] = 0; g_cursor[0] = 0; }
    if (i < N_NODES) {
        int r = g_rowoff[i + 1] + g_partial[i >> 8];
        g_rowoff[i + 1] = r;
        if (i + 1 < N_NODES) g_cursor[i + 1] = r;
    }
}

__global__ void k_scatter(const void* ei) {
    int e = blockIdx.x * blockDim.x + threadIdx.x;
    if (e >= N_EDGES) return;
    int is64 = g_is64;
    int s = edge_idx(ei, e, is64);
    int d = edge_idx(ei, (long long)N_EDGES + e, is64);
    int pos = atomicAdd(&g_cursor[d], 1);
    g_csr2[pos] = make_int2(s, __float_as_int(g_dinv[s] * g_dinv[d]));
}

// ---------------- aggregation: out = S · x  (128-dim) ---------------------
// out[d] = dinv[d]^2 * x[d] + sum_edges nrm * x[src]
// Block = 8 warps = 8 consecutive nodes. Their CSR segments form ONE
// contiguous range [rowoff[nb0], rowoff[nb0+8]) -> cooperatively loaded
// coalesced into smem once. Each warp then reads its indices via uniform
// LDS broadcasts (no long-scoreboard in the address path); gather groups
// of 8 issue back-to-back. Segments padded to mult of 8 with {0, 0.0f} ->
// inner loop mask-free, exact trip count.
__global__ void __launch_bounds__(256, 3)
k_agg128(const float* __restrict__ xin, float* __restrict__ out) {
    __shared__ int2 scsr[SEG_CAP];

    int nb0 = blockIdx.x * 8;            // 6250 blocks exactly
    int lane = threadIdx.x & 31;
    int wid = threadIdx.x >> 5;
    int d = nb0 + wid;
    if (d >= N_NODES) return;            // never taken (exact grid); safety

    int base = g_rowoff[nb0];
    int bend = g_rowoff[nb0 + 8];
    int range = bend - base;
    bool in_smem = (range <= SEG_CAP);

    if (in_smem) {
        for (int i = threadIdx.x; i < range; i += 256)
            scsr[i] = g_csr2[base + i];
    }
    __syncthreads();

    const float4* x4 = (const float4*)xin;

    float di = g_dinv[d];
    float sl = di * di;

    float4 v0 = x4[(long long)d * 32 + lane];
    float4 acc;
    acc.x = sl * v0.x; acc.y = sl * v0.y; acc.z = sl * v0.z; acc.w = sl * v0.w;

    if (in_smem) {
        int j0 = g_rowoff[d] - base;
        int j1 = g_rowoff[d + 1] - base;
        for (int j = j0; j < j1; j += 8) {
            int2 c0 = scsr[j + 0], c1 = scsr[j + 1];
            int2 c2 = scsr[j + 2], c3 = scsr[j + 3];
            int2 c4 = scsr[j + 4], c5 = scsr[j + 5];
            int2 c6 = scsr[j + 6], c7 = scsr[j + 7];

            float4 e0 = x4[(long long)c0.x * 32 + lane];
            float4 e1 = x4[(long long)c1.x * 32 + lane];
            float4 e2 = x4[(long long)c2.x * 32 + lane];
            float4 e3 = x4[(long long)c3.x * 32 + lane];
            float4 e4 = x4[(long long)c4.x * 32 + lane];
            float4 e5 = x4[(long long)c5.x * 32 + lane];
            float4 e6 = x4[(long long)c6.x * 32 + lane];
            float4 e7 = x4[(long long)c7.x * 32 + lane];

            float n0 = __int_as_float(c0.y), n1 = __int_as_float(c1.y);
            float n2 = __int_as_float(c2.y), n3 = __int_as_float(c3.y);
            float n4 = __int_as_float(c4.y), n5 = __int_as_float(c5.y);
            float n6 = __int_as_float(c6.y), n7 = __int_as_float(c7.y);

            acc.x += n0*e0.x + n1*e1.x + n2*e2.x + n3*e3.x
                   + n4*e4.x + n5*e5.x + n6*e6.x + n7*e7.x;
            acc.y += n0*e0.y + n1*e1.y + n2*e2.y + n3*e3.y
                   + n4*e4.y + n5*e5.y + n6*e6.y + n7*e7.y;
            acc.z += n0*e0.z + n1*e1.z + n2*e2.z + n3*e3.z
                   + n4*e4.z + n5*e5.z + n6*e6.z + n7*e7.z;
            acc.w += n0*e0.w + n1*e1.w + n2*e2.w + n3*e3.w
                   + n4*e4.w + n5*e5.w + n6*e6.w + n7*e7.w;
        }
    } else {
        // fallback (statistically never: range mean ~156, cap 1024)
        int j0 = g_rowoff[d];
        int j1 = g_rowoff[d + 1];
        for (int j = j0; j < j1; j += 8) {
            int2 c0 = g_csr2[j + 0], c1 = g_csr2[j + 1];
            int2 c2 = g_csr2[j + 2], c3 = g_csr2[j + 3];
            int2 c4 = g_csr2[j + 4], c5 = g_csr2[j + 5];
            int2 c6 = g_csr2[j + 6], c7 = g_csr2[j + 7];
            float4 e0 = x4[(long long)c0.x * 32 + lane];
            float4 e1 = x4[(long long)c1.x * 32 + lane];
            float4 e2 = x4[(long long)c2.x * 32 + lane];
            float4 e3 = x4[(long long)c3.x * 32 + lane];
            float4 e4 = x4[(long long)c4.x * 32 + lane];
            float4 e5 = x4[(long long)c5.x * 32 + lane];
            float4 e6 = x4[(long long)c6.x * 32 + lane];
            float4 e7 = x4[(long long)c7.x * 32 + lane];
            float n0 = __int_as_float(c0.y), n1 = __int_as_float(c1.y);
            float n2 = __int_as_float(c2.y), n3 = __int_as_float(c3.y);
            float n4 = __int_as_float(c4.y), n5 = __int_as_float(c5.y);
            float n6 = __int_as_float(c6.y), n7 = __int_as_float(c7.y);
            acc.x += n0*e0.x + n1*e1.x + n2*e2.x + n3*e3.x
                   + n4*e4.x + n5*e5.x + n6*e6.x + n7*e7.x;
            acc.y += n0*e0.y + n1*e1.y + n2*e2.y + n3*e3.y
                   + n4*e4.y + n5*e5.y + n6*e6.y + n7*e7.y;
            acc.z += n0*e0.z + n1*e1.z + n2*e2.z + n3*e3.z
                   + n4*e4.z + n5*e5.z + n6*e6.z + n7*e7.z;
            acc.w += n0*e0.w + n1*e1.w + n2*e2.w + n3*e3.w
                   + n4*e4.w + n5*e5.w + n6*e6.w + n7*e7.w;
        }
    }

    ((float4*)out)[(long long)d * 32 + lane] = acc;
}

// ---------------- dense GEMM + bias + relu: out = relu(X@W + b) -----------
template <int C>
__global__ void __launch_bounds__(256) k_gemm(const float* __restrict__ X,
                                              const float* __restrict__ W,
                                              const float* __restrict__ b,
                                              float* __restrict__ out) {
    __shared__ float Ws[128 * 64];
    __shared__ float Xt[128 * 32];

    const int col0 = blockIdx.y * 64;
    float4* Ws4 = (float4*)Ws;

    for (int i = threadIdx.x; i < 128 * 16; i += 256) {
        int k = i >> 4, t = i & 15;
        Ws4[i] = ((const float4*)(W + (long long)k * C + col0))[t];
    }

    const int tx = threadIdx.x & 15;
    const int ty = threadIdx.x >> 4;
    float4 bias = *(const float4*)(b + col0 + tx * 4);
    __syncthreads();

    const int ntiles = (N_NODES + 31) / 32;

    for (int tile = blockIdx.x; tile < ntiles; tile += gridDim.x) {
        int row0 = tile * 32;
        for (int i = threadIdx.x; i < 32 * 128; i += 256) {
            int r = i & 31, c = i >> 5;
            int row = row0 + r;
            Xt[c * 32 + r] = (row < N_NODES) ? X[(long long)row * 128 + c] : 0.f;
        }
        __syncthreads();

        float4 a0 = make_float4(0.f, 0.f, 0.f, 0.f);
        float4 a1 = make_float4(0.f, 0.f, 0.f, 0.f);

#pragma unroll 4
        for (int k = 0; k < 128; k++) {
            float4 w = Ws4[k * 16 + tx];
            float2 xp = *(const float2*)&Xt[k * 32 + 2 * ty];
            a0.x += xp.x * w.x; a0.y += xp.x * w.y;
            a0.z += xp.x * w.z; a0.w += xp.x * w.w;
            a1.x += xp.y * w.x; a1.y += xp.y * w.y;
            a1.z += xp.y * w.z; a1.w += xp.y * w.w;
        }

        a0.x = fmaxf(a0.x + bias.x, 0.f); a0.y = fmaxf(a0.y + bias.y, 0.f);
        a0.z = fmaxf(a0.z + bias.z, 0.f); a0.w = fmaxf(a0.w + bias.w, 0.f);
        a1.x = fmaxf(a1.x + bias.x, 0.f); a1.y = fmaxf(a1.y + bias.y, 0.f);
        a1.z = fmaxf(a1.z + bias.z, 0.f); a1.w = fmaxf(a1.w + bias.w, 0.f);

        int r0 = row0 + 2 * ty;
        int r1 = row0 + 2 * ty + 1;
        if (r0 < N_NODES)
            *(float4*)(out + (long long)r0 * C + col0 + tx * 4) = a0;
        if (r1 < N_NODES)
            *(float4*)(out + (long long)r1 * C + col0 + tx * 4) = a1;
        __syncthreads();
    }
}

// ---------------- attention pooling ----------------
__global__ void k_logits(const float* __restrict__ emb,
                         const float* __restrict__ Wa,
                         const float* __restrict__ ba) {
    __shared__ float smax[8];
    int lane = threadIdx.x & 31;
    int wid = threadIdx.x >> 5;
    int d = blockIdx.x * 8 + wid;

    const float4* e4 = (const float4*)(emb + (long long)d * C2);
    const float4* w4 = (const float4*)Wa;
    float s = 0.f;
#pragma unroll
    for (int j = 0; j < 2; j++) {
        float4 e = e4[lane + 32 * j];
        float4 w = w4[lane + 32 * j];
        s += e.x * w.x + e.y * w.y + e.z * w.z + e.w * w.w;
    }
#pragma unroll
    for (int o = 16; o > 0; o >>= 1) s += __shfl_xor_sync(0xffffffffu, s, o);
    float l = s + ba[0];
    if (lane == 0) { g_logits[d] = l; smax[wid] = l; }
    __syncthreads();
    if (threadIdx.x == 0) {
        float m = smax[0];
#pragma unroll
        for (int i = 1; i < 8; i++) m = fmaxf(m, smax[i]);
        atomicMax(&g_maxkey, enc_f(m));
    }
}

__global__ void k_exp(float* gout) {
    __shared__ float sh[256];
    int t = threadIdx.x;
    int i = blockIdx.x * 256 + t;
    if (blockIdx.x == 0) gout[t] = 0.f;
    float m = dec_f(g_maxkey);
    float p = 0.f;
    if (i < N_NODES) {
        p = expf(g_logits[i] - m);
        g_pw[i] = p;
    }
    sh[t] = p;
    __syncthreads();
    for (int off = 128; off > 0; off >>= 1) {
        if (t < off) sh[t] += sh[t + off];
        __syncthreads();
    }
    if (t == 0) atomicAdd(&g_sumexp, sh[0]);
}

__global__ void k_graph(const float* __restrict__ emb, float* __restrict__ gout) {
    int c = threadIdx.x;
    float acc = 0.f;
    for (int i = blockIdx.x; i < N_NODES; i += gridDim.x)
        acc += emb[(long long)i * C2 + c] * g_pw[i];
    atomicAdd(&gout[c], acc);
}

__global__ void k_scale(float* gout) {
    gout[threadIdx.x] *= (1.0f / g_sumexp);
}

// ---------------- launcher ----------------
extern "C" void kernel_launch(void* const* d_in, const int* in_sizes, int n_in,
                              void* d_out, int out_size) {
    const float* x  = (const float*)d_in[0];
    const void*  ei = d_in[1];
    const float* W1 = (const float*)d_in[2];
    const float* b1 = (const float*)d_in[3];
    const float* W2 = (const float*)d_in[4];
    const float* b2 = (const float*)d_in[5];
    const float* Wa = (const float*)d_in[6];
    const float* ba = (const float*)d_in[7];

    float* emb  = (float*)d_out;                              // (N, 256)
    float* gout = (float*)d_out + (long long)N_NODES * C2;    // (1, 256)

    k_sniff_init<<<NB_P, 256>>>(ei);                           // 0
    k_count<<<NB_E, 256>>>(ei);                                // 1
    k_scan1<<<NB_N, 256>>>();                                  // 2
    k_scan2<<<1, 256>>>();                                     // 3
    k_scan3<<<NB_N, 256>>>();                                  // 4
    k_scatter<<<NB_E, 256>>>(ei);                              // 5
    k_agg128<<<N_NODES / 8, 256>>>(x, g_aggx);                 // 6: S·X
    k_gemm<C1><<<dim3(296, 2), 256>>>(g_aggx, W1, b1, g_h1);   // 7
    k_agg128<<<N_NODES / 8, 256>>>(g_h1, g_aggh);              // 8: S·h
    k_gemm<C2><<<dim3(148, 4), 256>>>(g_aggh, W2, b2, emb);    // 9
    k_logits<<<N_NODES / 8, 256>>>(emb, Wa, ba);               // 10
    k_exp<<<NB_N, 256>>>(gout);                                // 11
    k_graph<<<512, 256>>>(emb, gout);                          // 12
    k_scale<<<1, 256>>>(gout);                                 // 13
}

// round 15
// speedup vs baseline: 1.0725x; 1.0120x over previous
#include <cuda_runtime.h>
#include <cuda_bf16.h>

#define N_NODES 50000
#define N_EDGES 800000
#define N_PAD   1150016                 // >= N_EDGES + 7*N_NODES, mult of 8
#define C1 128
#define C2 256
#define NB_N ((N_NODES + 255) / 256)   // 196
#define NB_E ((N_EDGES + 255) / 256)   // 3125
#define NB_P ((N_PAD + 255) / 256)

// ---------------- device scratch (static, no allocation) ----------------
__device__ int      g_is64;
__device__ int      g_degi[N_NODES];
__device__ float    g_dinv[N_NODES];
__device__ int      g_rowoff[N_NODES + 1];   // padded-CSR offsets (mult of 8)
__device__ int      g_cursor[N_NODES];
__device__ int      g_partial[256];
__device__ int2     g_csr2[N_PAD];           // {src, float_as_int(nrm)}
__device__ float    g_aggx[(long long)N_NODES * C1];  // S·X
__device__ float    g_h1[(long long)N_NODES * C1];    // relu(aggx·W1+b1)
__device__ float    g_aggh[(long long)N_NODES * C1];  // S·h1
__device__ float    g_logits[N_NODES];
__device__ float    g_pw[N_NODES];
__device__ unsigned g_maxkey;
__device__ float    g_sumexp;

// ---------------- helpers ----------------
__device__ __forceinline__ int edge_idx(const void* ei, long long i, int is64) {
    if (is64) return (int)((const long long*)ei)[i];
    return ((const int*)ei)[i];
}
__device__ __forceinline__ unsigned enc_f(float f) {
    unsigned u = __float_as_uint(f);
    return (u & 0x80000000u) ? ~u : (u | 0x80000000u);
}
__device__ __forceinline__ float dec_f(unsigned k) {
    unsigned u = (k & 0x80000000u) ? (k ^ 0x80000000u) : ~k;
    return __uint_as_float(u);
}

// ---------------- preprocessing ----------------
// launch 0: zero degi + zero the padded CSR (padding entries must be
// {src=0, nrm=0}); thread 0 sniffs edge dtype (int64 vs int32).
__global__ void k_sniff_init(const void* ei) {
    int i = blockIdx.x * blockDim.x + threadIdx.x;
    if (i < N_NODES) g_degi[i] = 0;
    if (i < N_PAD / 2) ((int4*)g_csr2)[i] = make_int4(0, 0, 0, 0);
    if (i == 0) {
        g_maxkey = 0u; g_sumexp = 0.f;
        const long long* p = (const long long*)ei;
        int ok = 1;
        for (int q = 0; q < 64; q++) {
            long long v = p[q];
            if (v < 0 || v >= N_NODES) { ok = 0; break; }
        }
        g_is64 = ok;
    }
}

__global__ void k_count(const void* ei) {
    int e = blockIdx.x * blockDim.x + threadIdx.x;
    if (e >= N_EDGES) return;
    int d = edge_idx(ei, (long long)N_EDGES + e, g_is64);
    atomicAdd(&g_degi[d], 1);
}

// per-block inclusive scan of PADDED degrees (ceil8) + dinv from real degree
__global__ void k_scan1() {
    __shared__ int sh[256];
    int t = threadIdx.x;
    int i = blockIdx.x * 256 + t;
    int v = (i < N_NODES) ? g_degi[i] : 0;
    if (i < N_NODES) g_dinv[i] = rsqrtf((float)(v + 1)); // +1 self loop
    int vp = (v + 7) & ~7;
    sh[t] = vp;
    __syncthreads();
    for (int off = 1; off < 256; off <<= 1) {
        int add = (t >= off) ? sh[t - off] : 0;
        __syncthreads();
        sh[t] += add;
        __syncthreads();
    }
    if (i < N_NODES) g_rowoff[i + 1] = sh[t];
    if (t == 255) g_partial[blockIdx.x] = sh[255];
}

__global__ void k_scan2() {
    __shared__ int sh[256];
    int t = threadIdx.x;
    int v = (t < NB_N) ? g_partial[t] : 0;
    sh[t] = v;
    __syncthreads();
    for (int off = 1; off < 256; off <<= 1) {
        int add = (t >= off) ? sh[t - off] : 0;
        __syncthreads();
        sh[t] += add;
        __syncthreads();
    }
    g_partial[t] = sh[t] - v; // exclusive
}

// final rowoff + cursor init (fused)
__global__ void k_scan3() {
    int i = blockIdx.x * blockDim.x + threadIdx.x;
    if (i == 0) { g_rowoff[0] = 0; g_cursor[0] = 0; }
    if (i < N_NODES) {
        int r = g_rowoff[i + 1] + g_partial[i >> 8];
        g_rowoff[i + 1] = r;
        if (i + 1 < N_NODES) g_cursor[i + 1] = r;
    }
}

__global__ void k_scatter(const void* ei) {
    int e = blockIdx.x * blockDim.x + threadIdx.x;
    if (e >= N_EDGES) return;
    int is64 = g_is64;
    int s = edge_idx(ei, e, is64);
    int d = edge_idx(ei, (long long)N_EDGES + e, is64);
    int pos = atomicAdd(&g_cursor[d], 1);
    g_csr2[pos] = make_int2(s, __float_as_int(g_dinv[s] * g_dinv[d]));
}

// ---------------- aggregation: out = S · x  (128-dim, warp per node) ------
// out[d] = dinv[d]^2 * x[d] + sum_edges nrm * x[src]
// CSR-vector with shuffle-staged indices (best measured variant, R11):
// each lane loads ONE csr entry of the node's segment (single coalesced
// LDG per 32 edges), then src/nrm broadcast via shfl (register pipe).
// Segments padded to mult of 8 with {0, 0.0f} -> inner loop mask-free.
__global__ void __launch_bounds__(256, 3)
k_agg128(const float* __restrict__ xin, float* __restrict__ out, int nlimit) {
    int d = (blockIdx.x * blockDim.x + threadIdx.x) >> 5;
    int lane = threadIdx.x & 31;
    if (d >= nlimit) return;

    const float4* x4 = (const float4*)xin;

    float di = g_dinv[d];
    float sl = di * di;

    float4 v0 = x4[(long long)d * 32 + lane];
    float4 acc;
    acc.x = sl * v0.x; acc.y = sl * v0.y; acc.z = sl * v0.z; acc.w = sl * v0.w;

    int j = g_rowoff[d];
    int end = g_rowoff[d + 1];

    for (int base = j; base < end; base += 32) {
        int idx = base + lane;
        int2 c = make_int2(0, 0);
        if (idx < end) c = g_csr2[idx];
        int cnt = end - base; cnt = (cnt > 32) ? 32 : cnt;  // multiple of 8

        for (int qq = 0; qq < cnt; qq += 8) {
            int s0 = __shfl_sync(0xffffffffu, c.x, qq + 0);
            int s1 = __shfl_sync(0xffffffffu, c.x, qq + 1);
            int s2 = __shfl_sync(0xffffffffu, c.x, qq + 2);
            int s3 = __shfl_sync(0xffffffffu, c.x, qq + 3);
            int s4 = __shfl_sync(0xffffffffu, c.x, qq + 4);
            int s5 = __shfl_sync(0xffffffffu, c.x, qq + 5);
            int s6 = __shfl_sync(0xffffffffu, c.x, qq + 6);
            int s7 = __shfl_sync(0xffffffffu, c.x, qq + 7);

            float4 e0 = x4[(long long)s0 * 32 + lane];
            float4 e1 = x4[(long long)s1 * 32 + lane];
            float4 e2 = x4[(long long)s2 * 32 + lane];
            float4 e3 = x4[(long long)s3 * 32 + lane];
            float4 e4 = x4[(long long)s4 * 32 + lane];
            float4 e5 = x4[(long long)s5 * 32 + lane];
            float4 e6 = x4[(long long)s6 * 32 + lane];
            float4 e7 = x4[(long long)s7 * 32 + lane];

            float n0 = __uint_as_float(__shfl_sync(0xffffffffu, c.y, qq + 0));
            float n1 = __uint_as_float(__shfl_sync(0xffffffffu, c.y, qq + 1));
            float n2 = __uint_as_float(__shfl_sync(0xffffffffu, c.y, qq + 2));
            float n3 = __uint_as_float(__shfl_sync(0xffffffffu, c.y, qq + 3));
            float n4 = __uint_as_float(__shfl_sync(0xffffffffu, c.y, qq + 4));
            float n5 = __uint_as_float(__shfl_sync(0xffffffffu, c.y, qq + 5));
            float n6 = __uint_as_float(__shfl_sync(0xffffffffu, c.y, qq + 6));
            float n7 = __uint_as_float(__shfl_sync(0xffffffffu, c.y, qq + 7));

            acc.x += n0*e0.x + n1*e1.x + n2*e2.x + n3*e3.x
                   + n4*e4.x + n5*e5.x + n6*e6.x + n7*e7.x;
            acc.y += n0*e0.y + n1*e1.y + n2*e2.y + n3*e3.y
                   + n4*e4.y + n5*e5.y + n6*e6.y + n7*e7.y;
            acc.z += n0*e0.z + n1*e1.z + n2*e2.z + n3*e3.z
                   + n4*e4.z + n5*e5.z + n6*e6.z + n7*e7.z;
            acc.w += n0*e0.w + n1*e1.w + n2*e2.w + n3*e3.w
                   + n4*e4.w + n5*e5.w + n6*e6.w + n7*e7.w;
        }
    }

    ((float4*)out)[(long long)d * 32 + lane] = acc;
}

// ---------------- dense GEMM + bias + relu: out = relu(X@W + b) -----------
template <int C>
__global__ void __launch_bounds__(256) k_gemm(const float* __restrict__ X,
                                              const float* __restrict__ W,
                                              const float* __restrict__ b,
                                              float* __restrict__ out) {
    __shared__ float Ws[128 * 64];
    __shared__ float Xt[128 * 32];

    const int col0 = blockIdx.y * 64;
    float4* Ws4 = (float4*)Ws;

    for (int i = threadIdx.x; i < 128 * 16; i += 256) {
        int k = i >> 4, t = i & 15;
        Ws4[i] = ((const float4*)(W + (long long)k * C + col0))[t];
    }

    const int tx = threadIdx.x & 15;
    const int ty = threadIdx.x >> 4;
    float4 bias = *(const float4*)(b + col0 + tx * 4);
    __syncthreads();

    const int ntiles = (N_NODES + 31) / 32;

    for (int tile = blockIdx.x; tile < ntiles; tile += gridDim.x) {
        int row0 = tile * 32;
        for (int i = threadIdx.x; i < 32 * 128; i += 256) {
            int r = i & 31, c = i >> 5;
            int row = row0 + r;
            Xt[c * 32 + r] = (row < N_NODES) ? X[(long long)row * 128 + c] : 0.f;
        }
        __syncthreads();

        float4 a0 = make_float4(0.f, 0.f, 0.f, 0.f);
        float4 a1 = make_float4(0.f, 0.f, 0.f, 0.f);

#pragma unroll 4
        for (int k = 0; k < 128; k++) {
            float4 w = Ws4[k * 16 + tx];
            float2 xp = *(const float2*)&Xt[k * 32 + 2 * ty];
            a0.x += xp.x * w.x; a0.y += xp.x * w.y;
            a0.z += xp.x * w.z; a0.w += xp.x * w.w;
            a1.x += xp.y * w.x; a1.y += xp.y * w.y;
            a1.z += xp.y * w.z; a1.w += xp.y * w.w;
        }

        a0.x = fmaxf(a0.x + bias.x, 0.f); a0.y = fmaxf(a0.y + bias.y, 0.f);
        a0.z = fmaxf(a0.z + bias.z, 0.f); a0.w = fmaxf(a0.w + bias.w, 0.f);
        a1.x = fmaxf(a1.x + bias.x, 0.f); a1.y = fmaxf(a1.y + bias.y, 0.f);
        a1.z = fmaxf(a1.z + bias.z, 0.f); a1.w = fmaxf(a1.w + bias.w, 0.f);

        int r0 = row0 + 2 * ty;
        int r1 = row0 + 2 * ty + 1;
        if (r0 < N_NODES)
            *(float4*)(out + (long long)r0 * C + col0 + tx * 4) = a0;
        if (r1 < N_NODES)
            *(float4*)(out + (long long)r1 * C + col0 + tx * 4) = a1;
        __syncthreads();
    }
}

// ---------------- attention pooling ----------------
__global__ void k_logits(const float* __restrict__ emb,
                         const float* __restrict__ Wa,
                         const float* __restrict__ ba) {
    __shared__ float smax[8];
    int lane = threadIdx.x & 31;
    int wid = threadIdx.x >> 5;
    int d = blockIdx.x * 8 + wid;

    const float4* e4 = (const float4*)(emb + (long long)d * C2);
    const float4* w4 = (const float4*)Wa;
    float s = 0.f;
#pragma unroll
    for (int j = 0; j < 2; j++) {
        float4 e = e4[lane + 32 * j];
        float4 w = w4[lane + 32 * j];
        s += e.x * w.x + e.y * w.y + e.z * w.z + e.w * w.w;
    }
#pragma unroll
    for (int o = 16; o > 0; o >>= 1) s += __shfl_xor_sync(0xffffffffu, s, o);
    float l = s + ba[0];
    if (lane == 0) { g_logits[d] = l; smax[wid] = l; }
    __syncthreads();
    if (threadIdx.x == 0) {
        float m = smax[0];
#pragma unroll
        for (int i = 1; i < 8; i++) m = fmaxf(m, smax[i]);
        atomicMax(&g_maxkey, enc_f(m));
    }
}

__global__ void k_exp(float* gout) {
    __shared__ float sh[256];
    int t = threadIdx.x;
    int i = blockIdx.x * 256 + t;
    if (blockIdx.x == 0) gout[t] = 0.f;
    float m = dec_f(g_maxkey);
    float p = 0.f;
    if (i < N_NODES) {
        p = expf(g_logits[i] - m);
        g_pw[i] = p;
    }
    sh[t] = p;
    __syncthreads();
    for (int off = 128; off > 0; off >>= 1) {
        if (t < off) sh[t] += sh[t + off];
        __syncthreads();
    }
    if (t == 0) atomicAdd(&g_sumexp, sh[0]);
}

__global__ void k_graph(const float* __restrict__ emb, float* __restrict__ gout) {
    int c = threadIdx.x;
    float acc = 0.f;
    for (int i = blockIdx.x; i < N_NODES; i += gridDim.x)
        acc += emb[(long long)i * C2 + c] * g_pw[i];
    atomicAdd(&gout[c], acc);
}

__global__ void k_scale(float* gout) {
    gout[threadIdx.x] *= (1.0f / g_sumexp);
}

// ---------------- launcher ----------------
extern "C" void kernel_launch(void* const* d_in, const int* in_sizes, int n_in,
                              void* d_out, int out_size) {
    const float* x  = (const float*)d_in[0];
    const void*  ei = d_in[1];
    const float* W1 = (const float*)d_in[2];
    const float* b1 = (const float*)d_in[3];
    const float* W2 = (const float*)d_in[4];
    const float* b2 = (const float*)d_in[5];
    const float* Wa = (const float*)d_in[6];
    const float* ba = (const float*)d_in[7];

    float* emb  = (float*)d_out;                              // (N, 256)
    float* gout = (float*)d_out + (long long)N_NODES * C2;    // (1, 256)

    k_sniff_init<<<NB_P, 256>>>(ei);                           // 0
    k_count<<<NB_E, 256>>>(ei);                                // 1
    k_scan1<<<NB_N, 256>>>();                                  // 2
    k_scan2<<<1, 256>>>();                                     // 3
    k_scan3<<<NB_N, 256>>>();                                  // 4
    k_scatter<<<NB_E, 256>>>(ei);                              // 5
    k_agg128<<<(N_NODES + 7) / 8, 256>>>(x, g_aggx, N_NODES);  // 6: S·X
    k_gemm<C1><<<dim3(296, 2), 256>>>(g_aggx, W1, b1, g_h1);   // 7
    k_agg128<<<(N_NODES + 7) / 8, 256>>>(g_h1, g_aggh, N_NODES); // 8: S·h
    k_gemm<C2><<<dim3(148, 4), 256>>>(g_aggh, W2, b2, emb);    // 9
    k_logits<<<N_NODES / 8, 256>>>(emb, Wa, ba);               // 10
    k_exp<<<NB_N, 256>>>(gout);                                // 11
    k_graph<<<512, 256>>>(emb, gout);                          // 12
    k_scale<<<1, 256>>>(gout);                                 // 13
}